// round 17
// baseline (speedup 1.0000x reference)
#include <cuda_runtime.h>
#include <cuda_fp16.h>
#include <cstdint>

// Problem constants
#define SEQ   4096
#define EMB   2048
#define NH    16
#define NKV   4
#define DHEAD 128
#define QKVD  3072   // packed q|k|v projection dim: 2048 + 512 + 512
#define NSPLIT 2     // split-KV factor in flash attention

// ---------------------------------------------------------------------------
// Scratch (device globals — no cudaMalloc allowed)
// ---------------------------------------------------------------------------
__device__ __half  g_wqkv[QKVD * EMB];        // packed [Wq;Wk;Wv] fp16
__device__ __half  g_wo[EMB * EMB];           // Wo fp16
__device__ __half  g_qkv[SEQ * QKVD];         // packed Q|K|V [4096,3072]
__device__ __half  g_po[NSPLIT * NH * SEQ * DHEAD];  // unnormalized O partials fp16
__device__ float   g_ml[NSPLIT * NH * SEQ * 2];      // (m, l) per row per split
__device__ float2  g_w[NH * SEQ];                    // combine weights (w0, w1)

// ---------------------------------------------------------------------------
// Helpers
// ---------------------------------------------------------------------------
__device__ __forceinline__ unsigned smem_u32(const void* p) {
    return (unsigned)__cvta_generic_to_shared(p);
}

__device__ __forceinline__ void cp_async16(void* smem, const void* gmem) {
    asm volatile("cp.async.cg.shared.global [%0], [%1], 16;\n"
                 :: "r"(smem_u32(smem)), "l"(gmem));
}
__device__ __forceinline__ void cp_commit() {
    asm volatile("cp.async.commit_group;\n");
}
template <int N>
__device__ __forceinline__ void cp_wait() {
    asm volatile("cp.async.wait_group %0;\n" :: "n"(N));
}

__device__ __forceinline__ void ldm_x4(unsigned& r0, unsigned& r1,
                                       unsigned& r2, unsigned& r3, unsigned addr) {
    asm volatile("ldmatrix.sync.aligned.m8n8.x4.shared.b16 {%0,%1,%2,%3}, [%4];"
                 : "=r"(r0), "=r"(r1), "=r"(r2), "=r"(r3) : "r"(addr));
}
__device__ __forceinline__ void ldm_x4_t(unsigned& r0, unsigned& r1,
                                         unsigned& r2, unsigned& r3, unsigned addr) {
    asm volatile("ldmatrix.sync.aligned.m8n8.x4.trans.shared.b16 {%0,%1,%2,%3}, [%4];"
                 : "=r"(r0), "=r"(r1), "=r"(r2), "=r"(r3) : "r"(addr));
}
__device__ __forceinline__ void mma16816(float* c, const unsigned* a,
                                         unsigned b0, unsigned b1) {
    asm volatile(
        "mma.sync.aligned.m16n8k16.row.col.f32.f16.f16.f32 "
        "{%0,%1,%2,%3}, {%4,%5,%6,%7}, {%8,%9}, {%0,%1,%2,%3};"
        : "+f"(c[0]), "+f"(c[1]), "+f"(c[2]), "+f"(c[3])
        : "r"(a[0]), "r"(a[1]), "r"(a[2]), "r"(a[3]), "r"(b0), "r"(b1));
}

// ---------------------------------------------------------------------------
// fp32 -> fp16 convert of the four WEIGHT matrices only (x is consumed fp32
// directly by gemm1). Region table in float4 units; 32B per thread.
//   Wq : [0,       1048576) -> g_wqkv + 0
//   Wk : [1048576, 1310720) -> g_wqkv + 4194304
//   Wv : [1310720, 1572864) -> g_wqkv + 5242880
//   Wo : [1572864, 2621440) -> g_wo
// ---------------------------------------------------------------------------
__global__ void cvt_w(const float* __restrict__ wq, const float* __restrict__ wk,
                      const float* __restrict__ wv, const float* __restrict__ wo,
                      __half* __restrict__ wqkv, __half* __restrict__ woh)
{
    int u = (blockIdx.x * blockDim.x + threadIdx.x) * 2;
    const float* src; __half* dst; int off;
    if (u < 1048576)       { src = wq; dst = wqkv;           off = u; }
    else if (u < 1310720)  { src = wk; dst = wqkv + 4194304; off = u - 1048576; }
    else if (u < 1572864)  { src = wv; dst = wqkv + 5242880; off = u - 1310720; }
    else                   { src = wo; dst = woh;            off = u - 1572864; }
    float4 v0 = reinterpret_cast<const float4*>(src)[off];
    float4 v1 = reinterpret_cast<const float4*>(src)[off + 1];
    __half2 h[4];
    h[0] = __floats2half2_rn(v0.x, v0.y);
    h[1] = __floats2half2_rn(v0.z, v0.w);
    h[2] = __floats2half2_rn(v1.x, v1.y);
    h[3] = __floats2half2_rn(v1.z, v1.w);
    *reinterpret_cast<uint4*>(dst + (size_t)off * 4) = *reinterpret_cast<uint4*>(h);
}

// ---------------------------------------------------------------------------
// compute_w: turn per-split (m, l) into normalized combine weights (w0, w1).
// i indexes (h, q) over NH*SEQ = 65536 rows.
// ---------------------------------------------------------------------------
__global__ void compute_w(const float* __restrict__ ml, float2* __restrict__ w)
{
    int i = blockIdx.x * blockDim.x + threadIdx.x;
    const int R = NH * SEQ;
    float m0 = ml[2 * i],           l0 = ml[2 * i + 1];
    float m1 = ml[2 * (R + i)],     l1 = ml[2 * (R + i) + 1];
    float mx = fmaxf(m0, m1);
    float w0 = exp2f(m0 - mx), w1 = exp2f(m1 - mx);
    float inv = 1.f / (l0 * w0 + l1 * w1);
    w[i] = make_float2(w0 * inv, w1 * inv);
}

// ---------------------------------------------------------------------------
// NT GEMM: C[M,N] = A[M,K] @ B[N,K]^T, fp32 accumulate.
// B path: fp16 via 4-stage cp.async pipeline (unchanged).
// A path (new): LDG -> transform-in-registers -> STS, distance-1 prefetch.
//   AMODE 1: A is fp32 (x); convert to fp16 in flight.
//   AMODE 2: A is two fp16 split-KV partials po[sp][h][q][d] blended with
//            per-(h,q) fp32 weights Wb -> fused combine. h = k-chunk >> 2.
// BM=128, BN=128, BK=32, 256 threads (8 warps: 4 in M x 2 in N).
// Dynamic smem = 81920 B.
// ---------------------------------------------------------------------------
#define GSTG 5120   // 128*40 halfs per stage

template <int AMODE, bool OUT_HALF>
__global__ __launch_bounds__(256, 2) void gemm_nt(
    const void* __restrict__ Ap, const __half* __restrict__ B,
    const float2* __restrict__ Wb, void* __restrict__ Cp,
    int M, int N, int K)
{
    extern __shared__ __half gsm[];
    __half* As = gsm;
    __half* Bs = gsm + 4 * GSTG;

    const int tid = threadIdx.x;
    const int lane = tid & 31, wid = tid >> 5;
    const int wm = wid & 3, wn = wid >> 2;
    const int m0 = blockIdx.y * 128, n0 = blockIdx.x * 128;
    const int lr = lane & 7, sel = lane >> 3;

    const int nk = K >> 5;

    // per-thread A coordinates (fixed): two (row, col) pairs
    int arow[2], acol[2];
#pragma unroll
    for (int i = 0; i < 2; i++) {
        int v = tid + i * 256;
        arow[i] = v >> 2;
        acol[i] = (v & 3) * 8;
    }

    auto issueB = [&](int it) {
        int s = it & 3;
        __half* bs = Bs + s * GSTG;
        int k0 = it * 32;
#pragma unroll
        for (int i = 0; i < 2; i++) {
            int v = tid + i * 256;
            int row = v >> 2, col = (v & 3) * 8;
            cp_async16(&bs[row * 40 + col], B + (size_t)(n0 + row) * K + k0 + col);
        }
    };

    auto ldA = [&](int c, uint4 rg[2][2], float2 wg[2]) {
#pragma unroll
        for (int i = 0; i < 2; i++) {
            if (AMODE == 1) {
                const float* Af = (const float*)Ap;
                const float* p = Af + (size_t)(m0 + arow[i]) * K + c * 32 + acol[i];
                rg[i][0] = *reinterpret_cast<const uint4*>(p);
                rg[i][1] = *reinterpret_cast<const uint4*>(p + 4);
            } else {
                const __half* Ph = (const __half*)Ap;
                int h = c >> 2;                       // 4 chunks of 32 per head
                int d = ((c & 3) * 32) + acol[i];
                size_t idx = ((size_t)h * SEQ + m0 + arow[i]) * DHEAD + d;
                rg[i][0] = *reinterpret_cast<const uint4*>(Ph + idx);
                rg[i][1] = *reinterpret_cast<const uint4*>(
                    Ph + (size_t)NH * SEQ * DHEAD + idx);
                wg[i] = Wb[(size_t)h * SEQ + m0 + arow[i]];
            }
        }
    };

    auto stsA = [&](int c, uint4 rg[2][2], float2 wg[2]) {
        __half* as = As + (c & 3) * GSTG;
#pragma unroll
        for (int i = 0; i < 2; i++) {
            __half2 out[4];
            if (AMODE == 1) {
                float4 f0 = *reinterpret_cast<float4*>(&rg[i][0]);
                float4 f1 = *reinterpret_cast<float4*>(&rg[i][1]);
                out[0] = __floats2half2_rn(f0.x, f0.y);
                out[1] = __floats2half2_rn(f0.z, f0.w);
                out[2] = __floats2half2_rn(f1.x, f1.y);
                out[3] = __floats2half2_rn(f1.z, f1.w);
            } else {
                const __half2* ah = reinterpret_cast<const __half2*>(&rg[i][0]);
                const __half2* bh = reinterpret_cast<const __half2*>(&rg[i][1]);
#pragma unroll
                for (int j = 0; j < 4; j++) {
                    float2 fa = __half22float2(ah[j]);
                    float2 fb = __half22float2(bh[j]);
                    out[j] = __floats2half2_rn(fa.x * wg[i].x + fb.x * wg[i].y,
                                               fa.y * wg[i].x + fb.y * wg[i].y);
                }
            }
            *reinterpret_cast<uint4*>(&as[arow[i] * 40 + acol[i]]) =
                *reinterpret_cast<uint4*>(out);
        }
    };

    float acc[2][8][4];
#pragma unroll
    for (int mt = 0; mt < 2; mt++)
#pragma unroll
        for (int nt = 0; nt < 8; nt++)
#pragma unroll
            for (int j = 0; j < 4; j++) acc[mt][nt][j] = 0.f;

    // prologue: A chunk 0 to smem, chunk 1 held in regs; B stages 0-2 in flight
    uint4 a_cur[2][2], a_nxt[2][2];
    float2 w_cur[2], w_nxt[2];
    ldA(0, a_cur, w_cur);
    stsA(0, a_cur, w_cur);
    ldA(1, a_cur, w_cur);
    issueB(0); cp_commit();
    issueB(1); cp_commit();
    issueB(2); cp_commit();

    for (int i = 0; i < nk; i++) {
        cp_wait<2>();
        __syncthreads();           // B(i) visible; A(i) STS from iter i-1 visible
        if (i + 3 < nk) issueB(i + 3);
        cp_commit();
        if (i + 2 < nk) ldA(i + 2, a_nxt, w_nxt);

        const __half* as = As + (i & 3) * GSTG;
        const __half* bs = Bs + (i & 3) * GSTG;

#pragma unroll
        for (int ks = 0; ks < 32; ks += 16) {
            unsigned a[2][4];
#pragma unroll
            for (int mt = 0; mt < 2; mt++) {
                int row = wm * 32 + mt * 16 + lr + (sel & 1) * 8;
                int col = ks + (sel >> 1) * 8;
                ldm_x4(a[mt][0], a[mt][1], a[mt][2], a[mt][3],
                       smem_u32(&as[row * 40 + col]));
            }
#pragma unroll
            for (int np = 0; np < 4; np++) {
                unsigned b[4];
                int row = wn * 64 + np * 16 + lr + (sel >> 1) * 8;
                int col = ks + (sel & 1) * 8;
                ldm_x4(b[0], b[1], b[2], b[3], smem_u32(&bs[row * 40 + col]));
#pragma unroll
                for (int mt = 0; mt < 2; mt++) {
                    mma16816(acc[mt][2 * np], a[mt], b[0], b[1]);
                    mma16816(acc[mt][2 * np + 1], a[mt], b[2], b[3]);
                }
            }
        }

        if (i + 1 < nk) {
            stsA(i + 1, a_cur, w_cur);     // stage (i+1)&3, read next iter
#pragma unroll
            for (int x2 = 0; x2 < 2; x2++) {
                a_cur[x2][0] = a_nxt[x2][0];
                a_cur[x2][1] = a_nxt[x2][1];
                w_cur[x2] = w_nxt[x2];
            }
        }
    }

    const int g = lane >> 2, t = lane & 3;
#pragma unroll
    for (int mt = 0; mt < 2; mt++) {
#pragma unroll
        for (int nt = 0; nt < 8; nt++) {
            int row = m0 + wm * 32 + mt * 16 + g;
            int col = n0 + wn * 64 + nt * 8 + t * 2;
            if (OUT_HALF) {
                __half* C = (__half*)Cp;
                *reinterpret_cast<__half2*>(C + (size_t)row * N + col) =
                    __floats2half2_rn(acc[mt][nt][0], acc[mt][nt][1]);
                *reinterpret_cast<__half2*>(C + (size_t)(row + 8) * N + col) =
                    __floats2half2_rn(acc[mt][nt][2], acc[mt][nt][3]);
            } else {
                float* C = (float*)Cp;
                *reinterpret_cast<float2*>(C + (size_t)row * N + col) =
                    make_float2(acc[mt][nt][0], acc[mt][nt][1]);
                *reinterpret_cast<float2*>(C + (size_t)(row + 8) * N + col) =
                    make_float2(acc[mt][nt][2], acc[mt][nt][3]);
            }
        }
    }
}

// ---------------------------------------------------------------------------
// Flash attention with split-KV. grid = (SEQ/128, NH, NSPLIT), 256 threads.
// Writes UNnormalized fp16 O-partials + fp32 (m, l).
// Dynamic smem = (128 + 3*128) * 136 * 2 = 139264 B.
// ---------------------------------------------------------------------------
#define FSTG (128 * 136)  // one KV stage (K 64x136 + V 64x136) in halfs
#define KVHALF (SEQ / NSPLIT)

__global__ __launch_bounds__(256) void flash_attn(
    const __half* __restrict__ QKV, __half* __restrict__ PO, float* __restrict__ ML)
{
    extern __shared__ __half fsm[];
    __half* Qs  = fsm;            // 128*136
    __half* KVs = fsm + FSTG;     // 3 stages

    const int tid = threadIdx.x, lane = tid & 31, wid = tid >> 5;
    const int h = blockIdx.y;
    const int q0 = blockIdx.x * 128;
    const int sp = blockIdx.z;                      // KV split index
    const int kvh = h >> 2;                         // GQA repeat_interleave(4)
    const int lr = lane & 7, sel = lane >> 3;
    const int g = lane >> 2, t = lane & 3;

    const __half* qg = QKV + (size_t)q0 * QKVD + h * DHEAD;
    const __half* kg = QKV + 2048 + (size_t)kvh * DHEAD + (size_t)sp * KVHALF * QKVD;
    const __half* vg = QKV + 2560 + (size_t)kvh * DHEAD + (size_t)sp * KVHALF * QKVD;

    auto issueKV = [&](int it) {
        int s = it % 3;
        __half* ks = KVs + s * FSTG;
        __half* vs = ks + 64 * 136;
        int kv0 = it * 64;
#pragma unroll
        for (int i = 0; i < 4; i++) {
            int v = tid + i * 256;
            int row = v >> 4, col = (v & 15) * 8;
            cp_async16(&ks[row * 136 + col], kg + (size_t)(kv0 + row) * QKVD + col);
            cp_async16(&vs[row * 136 + col], vg + (size_t)(kv0 + row) * QKVD + col);
        }
    };

    // group 0: Q tile
#pragma unroll
    for (int i = 0; i < 8; i++) {
        int v = tid + i * 256;
        int row = v >> 4, col = (v & 15) * 8;
        cp_async16(&Qs[row * 136 + col], qg + (size_t)row * QKVD + col);
    }
    cp_commit();
    issueKV(0); cp_commit();
    issueKV(1); cp_commit();

    cp_wait<2>();
    __syncthreads();

    unsigned qf[8][4];
    {
        int row = wid * 16 + lr + (sel & 1) * 8;
#pragma unroll
        for (int kt = 0; kt < 8; kt++) {
            int col = kt * 16 + (sel >> 1) * 8;
            ldm_x4(qf[kt][0], qf[kt][1], qf[kt][2], qf[kt][3],
                   smem_u32(&Qs[row * 136 + col]));
        }
    }

    float oacc[16][4];
#pragma unroll
    for (int nt = 0; nt < 16; nt++)
#pragma unroll
        for (int j = 0; j < 4; j++) oacc[nt][j] = 0.f;

    float mrow0 = -1e30f, mrow1 = -1e30f;
    float lrow0 = 0.f, lrow1 = 0.f;
    const float scale = 0.1275174302f;   // (1/sqrt(128)) * log2(e)

    const int nkv = KVHALF / 64;
    for (int i = 0; i < nkv; i++) {
        cp_wait<1>();
        __syncthreads();
        if (i + 2 < nkv) issueKV(i + 2);
        cp_commit();

        int s = i % 3;
        const __half* Ks = KVs + s * FSTG;
        const __half* Vs = Ks + 64 * 136;

        // --- S = Q @ K^T  (16 x 64 per warp) ---
        float sacc[8][4];
#pragma unroll
        for (int nt = 0; nt < 8; nt++)
#pragma unroll
            for (int j = 0; j < 4; j++) sacc[nt][j] = 0.f;

#pragma unroll
        for (int kt = 0; kt < 8; kt++) {
#pragma unroll
            for (int np = 0; np < 4; np++) {
                unsigned b[4];
                int row = np * 16 + lr + (sel >> 1) * 8;
                int col = kt * 16 + (sel & 1) * 8;
                ldm_x4(b[0], b[1], b[2], b[3], smem_u32(&Ks[row * 136 + col]));
                mma16816(sacc[2 * np], qf[kt], b[0], b[1]);
                mma16816(sacc[2 * np + 1], qf[kt], b[2], b[3]);
            }
        }

        // --- online softmax (base-2 domain) ---
        float mnew0 = mrow0, mnew1 = mrow1;
#pragma unroll
        for (int nt = 0; nt < 8; nt++) {
#pragma unroll
            for (int j = 0; j < 4; j++) sacc[nt][j] *= scale;
            mnew0 = fmaxf(mnew0, fmaxf(sacc[nt][0], sacc[nt][1]));
            mnew1 = fmaxf(mnew1, fmaxf(sacc[nt][2], sacc[nt][3]));
        }
        mnew0 = fmaxf(mnew0, __shfl_xor_sync(0xffffffffu, mnew0, 1));
        mnew0 = fmaxf(mnew0, __shfl_xor_sync(0xffffffffu, mnew0, 2));
        mnew1 = fmaxf(mnew1, __shfl_xor_sync(0xffffffffu, mnew1, 1));
        mnew1 = fmaxf(mnew1, __shfl_xor_sync(0xffffffffu, mnew1, 2));

        float alpha0 = exp2f(mrow0 - mnew0);
        float alpha1 = exp2f(mrow1 - mnew1);
        float rsum0 = 0.f, rsum1 = 0.f;

        unsigned ph[4][4];
#pragma unroll
        for (int nt = 0; nt < 8; nt++) {
            float p0 = exp2f(sacc[nt][0] - mnew0);
            float p1 = exp2f(sacc[nt][1] - mnew0);
            float p2 = exp2f(sacc[nt][2] - mnew1);
            float p3 = exp2f(sacc[nt][3] - mnew1);
            rsum0 += p0 + p1;
            rsum1 += p2 + p3;
            __half2 h01 = __floats2half2_rn(p0, p1);
            __half2 h23 = __floats2half2_rn(p2, p3);
            int kt = nt >> 1;
            if ((nt & 1) == 0) {
                ph[kt][0] = *reinterpret_cast<unsigned*>(&h01);
                ph[kt][1] = *reinterpret_cast<unsigned*>(&h23);
            } else {
                ph[kt][2] = *reinterpret_cast<unsigned*>(&h01);
                ph[kt][3] = *reinterpret_cast<unsigned*>(&h23);
            }
        }
        rsum0 += __shfl_xor_sync(0xffffffffu, rsum0, 1);
        rsum0 += __shfl_xor_sync(0xffffffffu, rsum0, 2);
        rsum1 += __shfl_xor_sync(0xffffffffu, rsum1, 1);
        rsum1 += __shfl_xor_sync(0xffffffffu, rsum1, 2);

        lrow0 = lrow0 * alpha0 + rsum0;
        lrow1 = lrow1 * alpha1 + rsum1;
        mrow0 = mnew0;
        mrow1 = mnew1;

#pragma unroll
        for (int nt = 0; nt < 16; nt++) {
            oacc[nt][0] *= alpha0; oacc[nt][1] *= alpha0;
            oacc[nt][2] *= alpha1; oacc[nt][3] *= alpha1;
        }

        // --- O += P @ V ---
#pragma unroll
        for (int kt = 0; kt < 4; kt++) {
#pragma unroll
            for (int np = 0; np < 8; np++) {
                unsigned b[4];
                int row = kt * 16 + lr + (sel & 1) * 8;
                int col = np * 16 + (sel >> 1) * 8;
                ldm_x4_t(b[0], b[1], b[2], b[3], smem_u32(&Vs[row * 136 + col]));
                mma16816(oacc[2 * np], ph[kt], b[0], b[1]);
                mma16816(oacc[2 * np + 1], ph[kt], b[2], b[3]);
            }
        }
    }

    // --- epilogue: store UNnormalized fp16 partials + fp32 (m, l) per row ---
    const size_t rowbase = ((size_t)(sp * NH + h) * SEQ + q0 + wid * 16);
    __half* pg = PO + rowbase * DHEAD;
#pragma unroll
    for (int nt = 0; nt < 16; nt++) {
        int col = nt * 8 + t * 2;
        *reinterpret_cast<__half2*>(pg + (size_t)g * DHEAD + col) =
            __floats2half2_rn(oacc[nt][0], oacc[nt][1]);
        *reinterpret_cast<__half2*>(pg + (size_t)(g + 8) * DHEAD + col) =
            __floats2half2_rn(oacc[nt][2], oacc[nt][3]);
    }
    if (t == 0) {
        ML[(rowbase + g) * 2 + 0] = mrow0;
        ML[(rowbase + g) * 2 + 1] = lrow0;
        ML[(rowbase + g + 8) * 2 + 0] = mrow1;
        ML[(rowbase + g + 8) * 2 + 1] = lrow1;
    }
}

// ---------------------------------------------------------------------------
// kernel_launch
// ---------------------------------------------------------------------------
extern "C" void kernel_launch(void* const* d_in, const int* in_sizes, int n_in,
                              void* d_out, int out_size) {
    (void)in_sizes; (void)n_in; (void)out_size;
    const float* x  = (const float*)d_in[0];
    const float* Wq = (const float*)d_in[1];
    const float* Wk = (const float*)d_in[2];
    const float* Wv = (const float*)d_in[3];
    const float* Wo = (const float*)d_in[4];

    void *wqkv, *wo, *qkv, *po, *ml, *w;
    cudaGetSymbolAddress(&wqkv, g_wqkv);
    cudaGetSymbolAddress(&wo,   g_wo);
    cudaGetSymbolAddress(&qkv,  g_qkv);
    cudaGetSymbolAddress(&po,   g_po);
    cudaGetSymbolAddress(&ml,   g_ml);
    cudaGetSymbolAddress(&w,    g_w);

    const int gemm_smem  = 2 * 4 * GSTG * (int)sizeof(__half);   // 81920
    const int flash_smem = 4 * FSTG * (int)sizeof(__half);       // 139264
    cudaFuncSetAttribute((const void*)gemm_nt<1, true>,
                         cudaFuncAttributeMaxDynamicSharedMemorySize, gemm_smem);
    cudaFuncSetAttribute((const void*)gemm_nt<2, false>,
                         cudaFuncAttributeMaxDynamicSharedMemorySize, gemm_smem);
    cudaFuncSetAttribute((const void*)flash_attn,
                         cudaFuncAttributeMaxDynamicSharedMemorySize, flash_smem);

    // fp32 -> fp16 converts: weights only (x consumed fp32 by gemm1)
    cvt_w<<<5120, 256>>>(Wq, Wk, Wv, Wo, (__half*)wqkv, (__half*)wo);

    // fused QKV projection: [4096,3072] = X(fp32, cvt in-flight) @ [Wq;Wk;Wv]^T
    gemm_nt<1, true><<<dim3(QKVD / 128, SEQ / 128), 256, gemm_smem>>>(
        x, (const __half*)wqkv, nullptr, qkv, SEQ, QKVD, EMB);

    // attention (split-KV x2)
    flash_attn<<<dim3(SEQ / 128, NH, NSPLIT), 256, flash_smem>>>(
        (const __half*)qkv, (__half*)po, (float*)ml);

    // combine weights, then output projection with fused split-combine A-path
    compute_w<<<(NH * SEQ) / 256, 256>>>((const float*)ml, (float2*)w);
    gemm_nt<2, false><<<dim3(EMB / 128, SEQ / 128), 256, gemm_smem>>>(
        po, (const __half*)wo, (const float2*)w, d_out, SEQ, EMB, EMB);
}